// round 1
// baseline (speedup 1.0000x reference)
#include <cuda_runtime.h>

// Problem constants
#define BB 16
#define CC 256
#define HH 64
#define WW 64
#define EE 4
#define K9 9
#define EPS_BN 1e-5f

// Conv tiling
#define TC 32   // output channels per block
#define TP 16   // spatial tile (TP x TP outputs)
#define CK 8    // input-channel chunk staged in smem

// Scratch (no cudaMalloc allowed -> __device__ globals)
__device__ float g_y[(size_t)BB*CC*HH*WW];        // post cv1 activation  (64 MB)
__device__ float g_kern[(size_t)BB*CC*CC*K9];     // per-sample conv2 weights (37.7 MB)
__device__ float g_pool[BB*CC];
__device__ float g_rout[BB*EE];

// ---------------------------------------------------------------------------
// Fused 3x3 conv (stride 1, pad 1) + BN(eval) + SiLU (+ optional residual)
// grid: (16 spatial tiles, CC/TC, BB), block: 256 threads
// Each thread: 2x2 output pixels x 8 output channels = 32 accumulators.
// ---------------------------------------------------------------------------
template<bool PER_SAMPLE, bool RESID>
__global__ __launch_bounds__(256)
void conv3x3_fused(const float* __restrict__ in,   // [B,C,H,W]
                   const float* __restrict__ wt,   // [C,C,3,3] or [B,C,C,3,3]
                   const float* __restrict__ bg,
                   const float* __restrict__ bb,
                   const float* __restrict__ bm,
                   const float* __restrict__ bv,
                   const float* __restrict__ resid,
                   float* __restrict__ out)
{
    __shared__ float s_in[CK][18][20];   // halo tile, padded row stride
    __shared__ float s_w[CK][K9][TC];    // weights, cout contiguous

    const int tid  = threadIdx.x;
    const int b    = blockIdx.z;
    const int co0  = blockIdx.y * TC;
    const int tile = blockIdx.x;              // 0..15 -> 4x4 tile grid
    const int ty0  = (tile >> 2) * TP;
    const int tx0  = (tile & 3) * TP;

    const int cg  = tid >> 6;                 // 0..3 (8 couts each)
    const int pix = tid & 63;
    const int py  = (pix >> 3) << 1;          // 0..14 even
    const int px  = (pix & 7) << 1;

    const float* wbase = wt + (PER_SAMPLE ? (size_t)b * CC * CC * K9 : 0);

    float acc[2][2][8];
    #pragma unroll
    for (int i = 0; i < 2; i++)
        #pragma unroll
        for (int j = 0; j < 2; j++)
            #pragma unroll
            for (int c = 0; c < 8; c++) acc[i][j][c] = 0.f;

    for (int ci0 = 0; ci0 < CC; ci0 += CK) {
        __syncthreads();   // protect previous chunk's smem reads

        // stage input halo: CK x 18 x 18
        for (int i = tid; i < CK * 18 * 18; i += 256) {
            int ck = i / 324;
            int r  = (i - ck * 324) / 18;
            int c  = i - ck * 324 - r * 18;
            int gy = ty0 + r - 1;
            int gx = tx0 + c - 1;
            float v = 0.f;
            if ((unsigned)gy < (unsigned)HH && (unsigned)gx < (unsigned)WW)
                v = in[(((size_t)b * CC + (ci0 + ck)) * HH + gy) * WW + gx];
            s_in[ck][r][c] = v;
        }
        // stage weights: s_w[ck][k][co]
        for (int i = tid; i < CK * K9 * TC; i += 256) {
            int co  = i / (CK * K9);
            int rem = i - co * (CK * K9);
            int ck  = rem / K9;
            int k   = rem - ck * K9;
            s_w[ck][k][co] = wbase[((size_t)(co0 + co) * CC + (ci0 + ck)) * K9 + k];
        }
        __syncthreads();

        #pragma unroll 1
        for (int ck = 0; ck < CK; ck++) {
            float win[4][4];
            #pragma unroll
            for (int r = 0; r < 4; r++)
                #pragma unroll
                for (int c = 0; c < 4; c++)
                    win[r][c] = s_in[ck][py + r][px + c];

            #pragma unroll
            for (int k = 0; k < K9; k++) {
                const int kh = k / 3, kw = k % 3;
                // within a warp cg is uniform -> broadcast LDS.128 pair
                const float4* wp = reinterpret_cast<const float4*>(&s_w[ck][k][cg << 3]);
                float4 wa = wp[0], wb = wp[1];
                float w8[8] = {wa.x, wa.y, wa.z, wa.w, wb.x, wb.y, wb.z, wb.w};
                #pragma unroll
                for (int dy = 0; dy < 2; dy++)
                    #pragma unroll
                    for (int dx = 0; dx < 2; dx++) {
                        float v = win[dy + kh][dx + kw];
                        #pragma unroll
                        for (int j = 0; j < 8; j++)
                            acc[dy][dx][j] = fmaf(v, w8[j], acc[dy][dx][j]);
                    }
            }
        }
    }

    // epilogue: BN + SiLU (+ residual)
    #pragma unroll
    for (int j = 0; j < 8; j++) {
        int co = co0 + (cg << 3) + j;
        float scale = bg[co] * rsqrtf(bv[co] + EPS_BN);
        float shift = bb[co] - bm[co] * scale;
        #pragma unroll
        for (int dy = 0; dy < 2; dy++)
            #pragma unroll
            for (int dx = 0; dx < 2; dx++) {
                int oy = ty0 + py + dy, ox = tx0 + px + dx;
                size_t oidx = (((size_t)b * CC + co) * HH + oy) * WW + ox;
                float t = acc[dy][dx][j] * scale + shift;
                float v = t / (1.f + __expf(-t));      // SiLU
                if (RESID) v += resid[oidx];
                out[oidx] = v;
            }
    }
}

// ---------------------------------------------------------------------------
// Global average pool: one block per (b,c)
// ---------------------------------------------------------------------------
__global__ void pool_kernel(const float* __restrict__ y, float* __restrict__ pool)
{
    int bc = blockIdx.x;
    const float* p = y + (size_t)bc * HH * WW;
    float s = 0.f;
    for (int i = threadIdx.x; i < HH * WW; i += 256) s += p[i];
    __shared__ float sm[256];
    sm[threadIdx.x] = s;
    __syncthreads();
    for (int st = 128; st > 0; st >>= 1) {
        if (threadIdx.x < st) sm[threadIdx.x] += sm[threadIdx.x + st];
        __syncthreads();
    }
    if (threadIdx.x == 0) pool[bc] = sm[0] * (1.f / (HH * WW));
}

// ---------------------------------------------------------------------------
// Routing: sigmoid(pooled @ wr.T + br)  -> [B,E]
// ---------------------------------------------------------------------------
__global__ void routing_kernel(const float* __restrict__ pool,
                               const float* __restrict__ wr,
                               const float* __restrict__ br,
                               float* __restrict__ rout)
{
    int t = threadIdx.x;
    if (t >= BB * EE) return;
    int b = t / EE, e = t - b * EE;
    float s = br[e];
    for (int c = 0; c < CC; c++) s += pool[b * CC + c] * wr[e * CC + c];
    rout[t] = 1.f / (1.f + __expf(-s));
}

// ---------------------------------------------------------------------------
// Per-sample kernel bank: kern[b, :] = sum_e rout[b,e] * w_e[e, :]
// ---------------------------------------------------------------------------
__global__ void kern_kernel(const float* __restrict__ rout,
                            const float* __restrict__ we,
                            float* __restrict__ kern)
{
    const int CC94 = CC * CC * K9 / 4;     // 147456 float4 per sample
    const int N4   = BB * CC94;
    const float4* we4 = reinterpret_cast<const float4*>(we);
    float4* k4 = reinterpret_cast<float4*>(kern);
    for (int i = blockIdx.x * blockDim.x + threadIdx.x; i < N4;
         i += gridDim.x * blockDim.x) {
        int b = i / CC94;
        int j = i - b * CC94;
        float r0 = rout[b * EE + 0], r1 = rout[b * EE + 1];
        float r2 = rout[b * EE + 2], r3 = rout[b * EE + 3];
        float4 a0 = we4[0 * CC94 + j], a1 = we4[1 * CC94 + j];
        float4 a2 = we4[2 * CC94 + j], a3 = we4[3 * CC94 + j];
        float4 o;
        o.x = r0 * a0.x + r1 * a1.x + r2 * a2.x + r3 * a3.x;
        o.y = r0 * a0.y + r1 * a1.y + r2 * a2.y + r3 * a3.y;
        o.z = r0 * a0.z + r1 * a1.z + r2 * a2.z + r3 * a3.z;
        o.w = r0 * a0.w + r1 * a1.w + r2 * a2.w + r3 * a3.w;
        k4[i] = o;
    }
}

// ---------------------------------------------------------------------------
extern "C" void kernel_launch(void* const* d_in, const int* in_sizes, int n_in,
                              void* d_out, int out_size)
{
    (void)in_sizes; (void)n_in; (void)out_size;
    const float* x   = (const float*)d_in[0];
    const float* w1  = (const float*)d_in[1];
    const float* b1g = (const float*)d_in[2];
    const float* b1b = (const float*)d_in[3];
    const float* b1m = (const float*)d_in[4];
    const float* b1v = (const float*)d_in[5];
    const float* wr  = (const float*)d_in[6];
    const float* br  = (const float*)d_in[7];
    const float* we  = (const float*)d_in[8];
    const float* b2g = (const float*)d_in[9];
    const float* b2b = (const float*)d_in[10];
    const float* b2m = (const float*)d_in[11];
    const float* b2v = (const float*)d_in[12];
    float* out = (float*)d_out;

    float *y, *kern, *pool, *rout;
    cudaGetSymbolAddress((void**)&y,    g_y);
    cudaGetSymbolAddress((void**)&kern, g_kern);
    cudaGetSymbolAddress((void**)&pool, g_pool);
    cudaGetSymbolAddress((void**)&rout, g_rout);

    dim3 grid(16, CC / TC, BB);   // (spatial tiles, cout tiles, batch)

    // cv1: conv + BN1 + SiLU -> y
    conv3x3_fused<false, false><<<grid, 256>>>(x, w1, b1g, b1b, b1m, b1v,
                                               nullptr, y);
    // routing path
    pool_kernel<<<BB * CC, 256>>>(y, pool);
    routing_kernel<<<1, 64>>>(pool, wr, br, rout);
    kern_kernel<<<4608, 256>>>(rout, we, kern);
    // cv2: per-sample conv + BN2 + SiLU + residual(x) -> out
    conv3x3_fused<true, true><<<grid, 256>>>(y, kern, b2g, b2b, b2m, b2v,
                                             x, out);
}

// round 2
// speedup vs baseline: 1.1497x; 1.1497x over previous
#include <cuda_runtime.h>

// Problem constants
#define BB 16
#define CC 256
#define HH 64
#define WW 64
#define EE 4
#define K9 9
#define EPS_BN 1e-5f

// Conv tiling
#define TC 32   // output channels per block
#define TP 16   // spatial tile (TP x TP outputs)
#define CK 8    // input-channel chunk staged in smem

// Scratch (no cudaMalloc allowed -> __device__ globals)
__device__ float g_y[(size_t)BB*CC*HH*WW];        // post cv1 activation  (64 MB)
__device__ float g_kern[(size_t)BB*CC*CC*K9];     // per-sample conv2 weights (37.7 MB)
__device__ float g_pool[BB*CC];
__device__ float g_rout[BB*EE];

// packed f32x2 helpers (SASS FFMA2 — ptxas never emits this from C++)
__device__ __forceinline__ unsigned long long pack2(float v) {
    unsigned long long r;
    asm("mov.b64 %0, {%1, %1};" : "=l"(r) : "r"(__float_as_uint(v)));
    return r;
}
__device__ __forceinline__ void fma2(unsigned long long& acc,
                                     unsigned long long a, unsigned long long b) {
    asm("fma.rn.f32x2 %0, %1, %2, %0;" : "+l"(acc) : "l"(a), "l"(b));
}

// ---------------------------------------------------------------------------
// Fused 3x3 conv (stride 1, pad 1) + BN(eval) + SiLU (+ optional residual)
// grid: (16 spatial tiles, CC/TC, BB), block: 256 threads
// Each thread: 2x2 output pixels x 8 output channels = 16 packed accumulators.
// ---------------------------------------------------------------------------
template<bool PER_SAMPLE, bool RESID>
__global__ __launch_bounds__(256)
void conv3x3_fused(const float* __restrict__ in,   // [B,C,H,W]
                   const float* __restrict__ wt,   // [C,C,3,3] or [B,C,C,3,3]
                   const float* __restrict__ bg,
                   const float* __restrict__ bb,
                   const float* __restrict__ bm,
                   const float* __restrict__ bv,
                   const float* __restrict__ resid,
                   float* __restrict__ out)
{
    __shared__ float s_in[CK][18][20];   // halo tile, padded row stride
    __shared__ float s_w[CK][K9][TC];    // weights, cout contiguous

    const int tid  = threadIdx.x;
    const int b    = blockIdx.z;
    const int co0  = blockIdx.y * TC;
    const int tile = blockIdx.x;              // 0..15 -> 4x4 tile grid
    const int ty0  = (tile >> 2) * TP;
    const int tx0  = (tile & 3) * TP;

    const int cg  = tid >> 6;                 // 0..3 (8 couts each)
    const int pix = tid & 63;
    const int py  = (pix >> 3) << 1;          // 0..14 even
    const int px  = (pix & 7) << 1;

    const float* wbase = wt + (PER_SAMPLE ? (size_t)b * CC * CC * K9 : 0);

    // acc2[dy][dx][p] packs couts (2p, 2p+1) for pixel (py+dy, px+dx)
    unsigned long long acc2[2][2][4];
    #pragma unroll
    for (int i = 0; i < 2; i++)
        #pragma unroll
        for (int j = 0; j < 2; j++)
            #pragma unroll
            for (int p = 0; p < 4; p++) acc2[i][j][p] = 0ull;

    for (int ci0 = 0; ci0 < CC; ci0 += CK) {
        __syncthreads();   // protect previous chunk's smem reads

        // stage input halo: CK x 18 x 18
        for (int i = tid; i < CK * 18 * 18; i += 256) {
            int ck = i / 324;
            int r  = (i - ck * 324) / 18;
            int c  = i - ck * 324 - r * 18;
            int gy = ty0 + r - 1;
            int gx = tx0 + c - 1;
            float v = 0.f;
            if ((unsigned)gy < (unsigned)HH && (unsigned)gx < (unsigned)WW)
                v = in[(((size_t)b * CC + (ci0 + ck)) * HH + gy) * WW + gx];
            s_in[ck][r][c] = v;
        }
        // stage weights: s_w[ck][k][co]
        for (int i = tid; i < CK * K9 * TC; i += 256) {
            int co  = i / (CK * K9);
            int rem = i - co * (CK * K9);
            int ck  = rem / K9;
            int k   = rem - ck * K9;
            s_w[ck][k][co] = wbase[((size_t)(co0 + co) * CC + (ci0 + ck)) * K9 + k];
        }
        __syncthreads();

        #pragma unroll 1
        for (int ck = 0; ck < CK; ck++) {
            float win[4][4];
            #pragma unroll
            for (int r = 0; r < 4; r++)
                #pragma unroll
                for (int c = 0; c < 4; c++)
                    win[r][c] = s_in[ck][py + r][px + c];

            #pragma unroll
            for (int k = 0; k < K9; k++) {
                const int kh = k / 3, kw = k % 3;
                // 8 couts = 4 packed pairs, 64-bit loads from smem (cg uniform per warp)
                const unsigned long long* wp =
                    reinterpret_cast<const unsigned long long*>(&s_w[ck][k][cg << 3]);
                unsigned long long w0 = wp[0], w1 = wp[1], w2 = wp[2], w3 = wp[3];
                #pragma unroll
                for (int dy = 0; dy < 2; dy++)
                    #pragma unroll
                    for (int dx = 0; dx < 2; dx++) {
                        unsigned long long vv = pack2(win[dy + kh][dx + kw]);
                        fma2(acc2[dy][dx][0], vv, w0);
                        fma2(acc2[dy][dx][1], vv, w1);
                        fma2(acc2[dy][dx][2], vv, w2);
                        fma2(acc2[dy][dx][3], vv, w3);
                    }
            }
        }
    }

    // epilogue: BN + SiLU (+ residual)
    #pragma unroll
    for (int p = 0; p < 4; p++) {
        #pragma unroll
        for (int half = 0; half < 2; half++) {
            int j  = (p << 1) + half;
            int co = co0 + (cg << 3) + j;
            float scale = bg[co] * rsqrtf(bv[co] + EPS_BN);
            float shift = bb[co] - bm[co] * scale;
            #pragma unroll
            for (int dy = 0; dy < 2; dy++)
                #pragma unroll
                for (int dx = 0; dx < 2; dx++) {
                    float lo, hi;
                    asm("mov.b64 {%0, %1}, %2;"
                        : "=f"(lo), "=f"(hi) : "l"(acc2[dy][dx][p]));
                    float a = half ? hi : lo;
                    int oy = ty0 + py + dy, ox = tx0 + px + dx;
                    size_t oidx = (((size_t)b * CC + co) * HH + oy) * WW + ox;
                    float t = a * scale + shift;
                    float v = t / (1.f + __expf(-t));      // SiLU
                    if (RESID) v += resid[oidx];
                    out[oidx] = v;
                }
        }
    }
}

// ---------------------------------------------------------------------------
// Global average pool: one block per (b,c)
// ---------------------------------------------------------------------------
__global__ void pool_kernel(const float* __restrict__ y, float* __restrict__ pool)
{
    int bc = blockIdx.x;
    const float* p = y + (size_t)bc * HH * WW;
    float s = 0.f;
    for (int i = threadIdx.x; i < HH * WW; i += 256) s += p[i];
    __shared__ float sm[256];
    sm[threadIdx.x] = s;
    __syncthreads();
    for (int st = 128; st > 0; st >>= 1) {
        if (threadIdx.x < st) sm[threadIdx.x] += sm[threadIdx.x + st];
        __syncthreads();
    }
    if (threadIdx.x == 0) pool[bc] = sm[0] * (1.f / (HH * WW));
}

// ---------------------------------------------------------------------------
// Routing: sigmoid(pooled @ wr.T + br)  -> [B,E]
// ---------------------------------------------------------------------------
__global__ void routing_kernel(const float* __restrict__ pool,
                               const float* __restrict__ wr,
                               const float* __restrict__ br,
                               float* __restrict__ rout)
{
    int t = threadIdx.x;
    if (t >= BB * EE) return;
    int b = t / EE, e = t - b * EE;
    float s = br[e];
    for (int c = 0; c < CC; c++) s += pool[b * CC + c] * wr[e * CC + c];
    rout[t] = 1.f / (1.f + __expf(-s));
}

// ---------------------------------------------------------------------------
// Per-sample kernel bank: kern[b, :] = sum_e rout[b,e] * w_e[e, :]
// ---------------------------------------------------------------------------
__global__ void kern_kernel(const float* __restrict__ rout,
                            const float* __restrict__ we,
                            float* __restrict__ kern)
{
    const int CC94 = CC * CC * K9 / 4;     // 147456 float4 per sample
    const int N4   = BB * CC94;
    const float4* we4 = reinterpret_cast<const float4*>(we);
    float4* k4 = reinterpret_cast<float4*>(kern);
    for (int i = blockIdx.x * blockDim.x + threadIdx.x; i < N4;
         i += gridDim.x * blockDim.x) {
        int b = i / CC94;
        int j = i - b * CC94;
        float r0 = rout[b * EE + 0], r1 = rout[b * EE + 1];
        float r2 = rout[b * EE + 2], r3 = rout[b * EE + 3];
        float4 a0 = we4[0 * CC94 + j], a1 = we4[1 * CC94 + j];
        float4 a2 = we4[2 * CC94 + j], a3 = we4[3 * CC94 + j];
        float4 o;
        o.x = r0 * a0.x + r1 * a1.x + r2 * a2.x + r3 * a3.x;
        o.y = r0 * a0.y + r1 * a1.y + r2 * a2.y + r3 * a3.y;
        o.z = r0 * a0.z + r1 * a1.z + r2 * a2.z + r3 * a3.z;
        o.w = r0 * a0.w + r1 * a1.w + r2 * a2.w + r3 * a3.w;
        k4[i] = o;
    }
}

// ---------------------------------------------------------------------------
extern "C" void kernel_launch(void* const* d_in, const int* in_sizes, int n_in,
                              void* d_out, int out_size)
{
    (void)in_sizes; (void)n_in; (void)out_size;
    const float* x   = (const float*)d_in[0];
    const float* w1  = (const float*)d_in[1];
    const float* b1g = (const float*)d_in[2];
    const float* b1b = (const float*)d_in[3];
    const float* b1m = (const float*)d_in[4];
    const float* b1v = (const float*)d_in[5];
    const float* wr  = (const float*)d_in[6];
    const float* br  = (const float*)d_in[7];
    const float* we  = (const float*)d_in[8];
    const float* b2g = (const float*)d_in[9];
    const float* b2b = (const float*)d_in[10];
    const float* b2m = (const float*)d_in[11];
    const float* b2v = (const float*)d_in[12];
    float* out = (float*)d_out;

    float *y, *kern, *pool, *rout;
    cudaGetSymbolAddress((void**)&y,    g_y);
    cudaGetSymbolAddress((void**)&kern, g_kern);
    cudaGetSymbolAddress((void**)&pool, g_pool);
    cudaGetSymbolAddress((void**)&rout, g_rout);

    dim3 grid(16, CC / TC, BB);   // (spatial tiles, cout tiles, batch)

    // cv1: conv + BN1 + SiLU -> y
    conv3x3_fused<false, false><<<grid, 256>>>(x, w1, b1g, b1b, b1m, b1v,
                                               nullptr, y);
    // routing path
    pool_kernel<<<BB * CC, 256>>>(y, pool);
    routing_kernel<<<1, 64>>>(pool, wr, br, rout);
    kern_kernel<<<4608, 256>>>(rout, we, kern);
    // cv2: per-sample conv + BN2 + SiLU + residual(x) -> out
    conv3x3_fused<true, true><<<grid, 256>>>(y, kern, b2g, b2b, b2m, b2v,
                                             x, out);
}